// round 8
// baseline (speedup 1.0000x reference)
#include <cuda_runtime.h>
#include <cuda_bf16.h>
#include <math.h>

#define NV    6144
#define HV    4
#define EPSV  1e-7f
#define MINV  1e-15f
#define NSEG  32
#define SEGR  192
#define CAP   24
#define AST   68
#define WLN   320

// ---------------- scratch ----------------
__device__ int   g_cnt[NV * NSEG];
__device__ int   g_nbr[(size_t)NV * NSEG * CAP];
__device__ float g_att[(size_t)HV * NV * AST];  // [0..63] raw att ov; [64..67]=t_att,sh_att,t_dat,sh_dat
__device__ float g_dat[(size_t)HV * NV * AST];  // [0..63] raw dat ov
__device__ float g_osqF[16 * NV];               // k_feat partial osq [osel*8+m][node]
__device__ float g_u  [(size_t)HV * NV * 64];   // node-major mobius logmap vectors
__device__ float g_pcT[(size_t)256 * NV];       // feature-major RAW Wo outputs
__device__ float g_osqP[16 * NV];               // k_post1 partial osq [osel*4+h][node]
__device__ float g_as [HV * NV];                // fused per-(head,node) scale
__device__ float g_pre[(size_t)NV * WLN];
__device__ float g_WlP[256 * WLN];              // W_lin^T padded (zeros beyond 260)

// ---------------- helpers ----------------
__device__ __forceinline__ float wred(float v) {
#pragma unroll
    for (int o = 16; o; o >>= 1) v += __shfl_xor_sync(0xffffffffu, v, o);
    return v;
}
__device__ __forceinline__ float acoshr(float z) {          // precise (node-level uses)
    float t = fmaxf(z * z - 1.0f, 0.0f);
    return logf(z + sqrtf(t));
}
__device__ __forceinline__ float acoshf_fast(float z) {     // fast (per-edge hot path)
    float t = fmaxf(z * z - 1.0f, 0.0f);
    return __logf(z + sqrtf(t));
}

// ---------------- K1: neighbor lists + W_lin transpose ----------------
__global__ __launch_bounds__(256) void k_build(const float* __restrict__ adj,
                                               const float* __restrict__ Wl) {
    if (blockIdx.y == NSEG) {
        for (int e = blockIdx.x * 256 + threadIdx.x; e < 256 * 260; e += 24 * 256) {
            int kk = e / 260, n = e % 260;
            g_WlP[(size_t)kk * WLN + n] = Wl[n * 257 + kk + 1];
        }
        return;
    }
    int c   = blockIdx.x * 256 + threadIdx.x;
    int seg = blockIdx.y;
    int cnt = 0;
    size_t base = ((size_t)c * NSEG + seg) * CAP;
    int j0 = seg * SEGR;
    for (int r = 0; r < SEGR; r += 8) {
        float v[8];
#pragma unroll
        for (int u = 0; u < 8; u++) v[u] = adj[(size_t)(j0 + r + u) * NV + c];
#pragma unroll
        for (int u = 0; u < 8; u++) {
            if (v[u] > 0.01f) {
                if (cnt < CAP) g_nbr[base + cnt] = j0 + r + u;
                cnt++;
            }
        }
    }
    g_cnt[c * NSEG + seg] = (cnt < CAP) ? cnt : CAP;
}

// ---------------- K2: hyp_linear att/data -> RAW half-rows + partial osq ------
#define SMEM_FEAT ((8320 + 2048) * 4)

__global__ __launch_bounds__(128) void k_feat(const float* __restrict__ x,
                                              const float* __restrict__ Wa,
                                              const float* __restrict__ Wd) {
    extern __shared__ float sm[];
    float*  su  = sm;                 // 128*65
    float*  sW  = sm + 8320;          // 32*64
    float4* sW4 = (float4*)sW;
    int t = threadIdx.x;
    int m = blockIdx.y, h = m & 3, osel = blockIdx.z;
    const float* W = (m < 4) ? (Wa + h * 4225) : (Wd + h * 4225);
    int nb = blockIdx.x * 128;

    for (int e = t; e < 128 * 65; e += 128) su[e] = x[(size_t)nb * 65 + e];
    for (int e = t; e < 32 * 64; e += 128) {
        int oo = e >> 6, c = e & 63;
        sW[e] = W[(osel * 32 + oo + 1) * 65 + 1 + c];
    }
    __syncthreads();

    float u[64];
    float x0 = su[t * 65];
    float q0 = 0.f, q1 = 0.f, q2 = 0.f, q3 = 0.f;
#pragma unroll
    for (int c = 0; c < 64; c += 4) {
        float a = su[t * 65 + 1 + c], b = su[t * 65 + 2 + c];
        float cc = su[t * 65 + 3 + c], d = su[t * 65 + 4 + c];
        u[c] = a; u[c + 1] = b; u[c + 2] = cc; u[c + 3] = d;
        q0 += a * a; q1 += b * b; q2 += cc * cc; q3 += d * d;
    }
    float nsq = (q0 + q1) + (q2 + q3);
    float scale = acoshr(fmaxf(x0, 1.0f + EPSV)) / fmaxf(sqrtf(nsq), MINV);
#pragma unroll
    for (int c = 0; c < 64; c++) u[c] *= scale;

    float* dst = (m < 4) ? g_att : g_dat;
    float* R = dst + ((size_t)(h * NV) + nb + t) * AST + osel * 32;
    float osq = 0.f;
#pragma unroll 2
    for (int o4 = 0; o4 < 8; o4++) {
        float4 ov4;
        float* po = (float*)&ov4;
#pragma unroll
        for (int jj = 0; jj < 4; jj++) {
            int oo = o4 * 4 + jj;
            float a0 = 0.f, a1 = 0.f, a2 = 0.f, a3 = 0.f;
#pragma unroll
            for (int c4 = 0; c4 < 16; c4++) {
                float4 wv = sW4[oo * 16 + c4];
                a0 += wv.x * u[4 * c4];
                a1 += wv.y * u[4 * c4 + 1];
                a2 += wv.z * u[4 * c4 + 2];
                a3 += wv.w * u[4 * c4 + 3];
            }
            float ov = (a0 + a1) + (a2 + a3);
            po[jj] = ov;
            osq += ov * ov;
        }
        *(float4*)&R[o4 * 4] = ov4;
    }
    g_osqF[(osel * 8 + m) * NV + nb + t] = osq;
}

// ---------------- K2b: combine osq -> t/sh extras in g_att rows --------------
__global__ __launch_bounds__(256) void k_ts(void) {
    int node = blockIdx.x * 256 + threadIdx.x;
    int m = blockIdx.y, h = m & 3;
    float osq = g_osqF[m * NV + node] + g_osqF[(8 + m) * NV + node];
    float n2 = fmaxf(sqrtf(osq), MINV);
    float shv = sinhf(n2) / n2;
    float tv = sqrtf(1.0f + shv * shv * osq);
    float* R = g_att + ((size_t)(h * NV) + node) * AST + ((m < 4) ? 64 : 66);
    R[0] = tv;
    R[1] = shv;
}

// ---------------- K3: sparse attention + mobius, 2 warps per head ------------
__global__ __launch_bounds__(256) void k_attn(void) {
    int i = blockIdx.x;
    int t = threadIdx.x;
    int w = t >> 5, l = t & 31;
    int h = w >> 1, sub = w & 1;
    int s = l & 7, g = l >> 3;
    __shared__ int slist[800];
    __shared__ int stot;
    __shared__ float sT[8][66];

    if (t < 32) {
        int c = g_cnt[i * NSEG + l];
        int sc = c;
#pragma unroll
        for (int o = 1; o < 32; o <<= 1) {
            int v = __shfl_up_sync(0xffffffffu, sc, o);
            if (l >= o) sc += v;
        }
        int off = sc - c;
        const int* lst = g_nbr + ((size_t)i * NSEG + l) * CAP;
        for (int k = 0; k < c; k++) slist[off + k] = lst[k];
        if (l == 31) stot = sc;
    }
    __syncthreads();
    int nk = stot;
    int nk4 = (nk + 3) & ~3;
    if (t < nk4 - nk) slist[nk + t] = slist[0];
    __syncthreads();

    const float* Ai = g_att + ((size_t)(h * NV) + i) * AST;
    float4 ei = *(const float4*)(Ai + 64);   // t_att, sh_att, t_dat, sh_dat
    float ai0 = ei.x, shA_i = ei.y;
    float4 a0 = *(const float4*)(Ai + 8 * s);
    float4 a1 = *(const float4*)(Ai + 8 * s + 4);
    a0.x *= shA_i; a0.y *= shA_i; a0.z *= shA_i; a0.w *= shA_i;
    a1.x *= shA_i; a1.y *= shA_i; a1.z *= shA_i; a1.w *= shA_i;

    float T1 = 0.f, T2 = 0.f, Up = 0.f, Qp = 0.f;
    // sub-warp strided over neighbor groups of 4
    for (int kc = sub * 4; kc < nk4; kc += 8) {
        int j = slist[kc + g];
        const float* Aj = g_att + ((size_t)(h * NV) + j) * AST;
        float4 b0 = *(const float4*)(Aj + 8 * s);
        float4 b1 = *(const float4*)(Aj + 8 * s + 4);
        float4 ej = *(const float4*)(Aj + 64);
        float part = a0.x * b0.x + a0.y * b0.y + a0.z * b0.z + a0.w * b0.w
                   + a1.x * b1.x + a1.y * b1.y + a1.z * b1.z + a1.w * b1.w;
#pragma unroll
        for (int o = 4; o; o >>= 1) part += __shfl_xor_sync(0xffffffffu, part, o);
        float th = fmaxf(ai0 * ej.x - ej.y * part, 1.0f + EPSV);
        float ar = acoshf_fast(th);
        float S = fminf(ar * ar, 50.0f);
        if (kc + g >= nk) S = 0.0f;
        Up += S * ej.z;          // S * (lam-1) = S * t_dat
        Qp += S * S;
        float Sgs = S * ej.w;    // S * sh_dat
#pragma unroll
        for (int gg = 0; gg < 4; gg++) {
            float Sg = __shfl_sync(0xffffffffu, Sgs, gg * 8 + s);
            int jg = slist[kc + gg];
            const float* Dj = g_dat + ((size_t)(h * NV) + jg) * AST;
            T1 += Sg * Dj[l];
            T2 += Sg * Dj[l + 32];
        }
    }
    // per-warp scalar partials
    float Uw = wred(Up) * 0.125f;
    float Qw = wred(Qp) * 0.125f;
    sT[w][l] = T1;
    sT[w][32 + l] = T2;
    if (l == 0) { sT[w][64] = Uw; sT[w][65] = Qw; }
    __syncthreads();

    if (sub == 0) {
        // combine pair (deterministic fixed order)
        float T1c = sT[2 * h][l]      + sT[2 * h + 1][l];
        float T2c = sT[2 * h][32 + l] + sT[2 * h + 1][32 + l];
        float U   = sT[2 * h][64]     + sT[2 * h + 1][64];
        float Q   = sT[2 * h][65]     + sT[2 * h + 1][65];

        float nrm = fmaxf(sqrtf(Q), 1e-12f);
        float den = fmaxf(U / nrm, MINV);
        float v1 = (-T1c / nrm) / den, v2 = (-T2c / nrm) / den;
        float nvsq = wred(v1 * v1 + v2 * v2);
        float nv = fmaxf(sqrtf(nvsq), MINV);
        float ncl = fminf(nv, 1.0f - EPSV);
        float f = tanhf(0.5f * atanhf(ncl)) / nv;
        float m1 = f * v1, m2 = f * v2;
        float s2 = f * f * nvsq;
        float dd = fmaxf(1.0f - s2, MINV);
        float hb0 = (1.0f + s2) / dd;
        float nyy = fmaxf(2.0f * sqrtf(s2) / dd, MINV);
        float sc2 = acoshr(fmaxf(hb0, 1.0f + EPSV)) * (2.0f / dd) / nyy;
        float* Uo = g_u + ((size_t)(h * NV) + i) * 64;
        Uo[l]      = sc2 * m1;
        Uo[l + 32] = sc2 * m2;
    }
}

// ---------------- K4: Wo matvec, node-per-thread, 4-way o-split --------------
__global__ __launch_bounds__(128) void k_post1(const float* __restrict__ Wo) {
    __shared__ float sW[16 * 64];
    float4* sW4 = (float4*)sW;
    int t = threadIdx.x;
    int h = blockIdx.y, osel = blockIdx.z;
    int node = blockIdx.x * 128 + t;

    for (int e = t; e < 16 * 64; e += 128) {
        int o2 = e >> 6, c = e & 63;
        sW[e] = Wo[h * 4225 + (osel * 16 + o2 + 1) * 65 + 1 + c];
    }
    __syncthreads();

    float u[64];
    const float4* U4 = (const float4*)(g_u + ((size_t)(h * NV) + node) * 64);
#pragma unroll
    for (int c4 = 0; c4 < 16; c4++) {
        float4 v = U4[c4];
        u[4 * c4] = v.x; u[4 * c4 + 1] = v.y; u[4 * c4 + 2] = v.z; u[4 * c4 + 3] = v.w;
    }

    float osq = 0.f;
#pragma unroll 2
    for (int o2 = 0; o2 < 16; o2++) {
        float a0 = 0.f, a1 = 0.f, a2 = 0.f, a3 = 0.f;
#pragma unroll
        for (int c4 = 0; c4 < 16; c4++) {
            float4 wv = sW4[o2 * 16 + c4];
            a0 += wv.x * u[4 * c4];
            a1 += wv.y * u[4 * c4 + 1];
            a2 += wv.z * u[4 * c4 + 2];
            a3 += wv.w * u[4 * c4 + 3];
        }
        float ov = (a0 + a1) + (a2 + a3);
        g_pcT[(size_t)(h * 64 + osel * 16 + o2) * NV + node] = ov;
        osq += ov * ov;
    }
    g_osqP[(osel * 4 + h) * NV + node] = osq;
}

// ---------------- K5: fused per-(head,node) scale ----------------
__global__ __launch_bounds__(256) void k_scal(void) {
    int node = blockIdx.x * 256 + threadIdx.x;
    float cn[HV];
    float ssum = 0.f;
#pragma unroll
    for (int h = 0; h < HV; h++) {
        float osq = g_osqP[h * NV + node] + g_osqP[(4 + h) * NV + node]
                  + g_osqP[(8 + h) * NV + node] + g_osqP[(12 + h) * NV + node];
        float n2 = fmaxf(sqrtf(osq), MINV);
        float sh = sinhf(n2) / n2;
        float tv = sqrtf(1.0f + sh * sh * osq);
        cn[h] = sh / (tv + 1.0f);
        ssum += cn[h] * cn[h] * osq;
    }
    float dd = fmaxf(1.0f - ssum, MINV);
    float hb0 = (1.0f + ssum) / dd;
    float nyy = fmaxf(2.0f * sqrtf(ssum) / dd, MINV);
    float srow = acoshr(fmaxf(hb0, 1.0f + EPSV)) * (2.0f / dd) / nyy;
#pragma unroll
    for (int h = 0; h < HV; h++) g_as[h * NV + node] = cn[h] * srow;
}

// ---------------- K6: SGEMM 64x64x16, scale fused on A load ------------------
__global__ __launch_bounds__(256) void k_lin(void) {
    __shared__ float As[16][68];
    __shared__ float Bs[16][64];
    __shared__ float sAS[4][64];
    int t = threadIdx.x;
    int i0 = blockIdx.x * 64, n0 = blockIdx.y * 64;
    int tx = t & 15, ty = t >> 4;
    int ak = t >> 4, an4 = t & 15;
    float acc[4][4];
#pragma unroll
    for (int i = 0; i < 4; i++)
#pragma unroll
        for (int j = 0; j < 4; j++) acc[i][j] = 0.f;

    {
        int h = t >> 6, n = t & 63;
        sAS[h][n] = g_as[h * NV + i0 + n];
    }
    __syncthreads();

    for (int k0 = 0; k0 < 256; k0 += 16) {
        int hh = k0 >> 6;
        __syncthreads();
        float4 av = *(const float4*)&g_pcT[(size_t)(k0 + ak) * NV + i0 + an4 * 4];
        float4 sv = *(const float4*)&sAS[hh][an4 * 4];
        As[ak][an4 * 4 + 0] = av.x * sv.x;
        As[ak][an4 * 4 + 1] = av.y * sv.y;
        As[ak][an4 * 4 + 2] = av.z * sv.z;
        As[ak][an4 * 4 + 3] = av.w * sv.w;
        *(float4*)&Bs[ak][an4 * 4] =
            *(const float4*)&g_WlP[(size_t)(k0 + ak) * WLN + n0 + an4 * 4];
        __syncthreads();
#pragma unroll
        for (int k = 0; k < 16; k++) {
            float4 a = *(const float4*)&As[k][ty * 4];
            float4 b = *(const float4*)&Bs[k][tx * 4];
            acc[0][0] += a.x * b.x; acc[0][1] += a.x * b.y; acc[0][2] += a.x * b.z; acc[0][3] += a.x * b.w;
            acc[1][0] += a.y * b.x; acc[1][1] += a.y * b.y; acc[1][2] += a.y * b.z; acc[1][3] += a.y * b.w;
            acc[2][0] += a.z * b.x; acc[2][1] += a.z * b.y; acc[2][2] += a.z * b.z; acc[2][3] += a.z * b.w;
            acc[3][0] += a.w * b.x; acc[3][1] += a.w * b.y; acc[3][2] += a.w * b.z; acc[3][3] += a.w * b.w;
        }
    }
#pragma unroll
    for (int i = 0; i < 4; i++) {
        float4 v = make_float4(acc[i][0], acc[i][1], acc[i][2], acc[i][3]);
        *(float4*)&g_pre[(size_t)(i0 + ty * 4 + i) * WLN + n0 + tx * 4] = v;
    }
}

// ---------------- K7: final expmap0 + hyp_proj ----------------
__global__ __launch_bounds__(256) void k_final(float* __restrict__ out) {
    int w = threadIdx.x >> 5, l = threadIdx.x & 31;
    int row = blockIdx.x * 8 + w;
    float v[8], q = 0.f;
#pragma unroll
    for (int k = 0; k < 8; k++) {
        v[k] = g_pre[(size_t)row * WLN + k * 32 + l];
        if (!(k == 0 && l == 0)) q += v[k] * v[k];
    }
    float t4 = 0.f;
    if (l < 4) { t4 = g_pre[(size_t)row * WLN + 256 + l]; q += t4 * t4; }
    q = wred(q);
    float n2 = fmaxf(sqrtf(q), MINV);
    float sh = sinhf(n2) / n2;
    float tv = sqrtf(1.0f + sh * sh * q);
#pragma unroll
    for (int k = 0; k < 8; k++) {
        float o = (k == 0 && l == 0) ? tv : sh * v[k];
        out[(size_t)row * 260 + k * 32 + l] = o;
    }
    if (l < 4) out[(size_t)row * 260 + 256 + l] = sh * t4;
}

// ---------------- launch ----------------
extern "C" void kernel_launch(void* const* d_in, const int* in_sizes, int n_in,
                              void* d_out, int out_size) {
    const float* x     = (const float*)d_in[0];
    const float* adj   = (const float*)d_in[1];
    const float* W_att = (const float*)d_in[2];
    const float* W_dat = (const float*)d_in[3];
    const float* W_out = (const float*)d_in[4];
    const float* W_lin = (const float*)d_in[5];
    float* out = (float*)d_out;

    cudaFuncSetAttribute(k_feat, cudaFuncAttributeMaxDynamicSharedMemorySize, SMEM_FEAT);

    k_build<<<dim3(NV / 256, NSEG + 1), 256>>>(adj, W_lin);
    k_feat<<<dim3(NV / 128, 8, 2), 128, SMEM_FEAT>>>(x, W_att, W_dat);
    k_ts<<<dim3(NV / 256, 8), 256>>>();
    k_attn<<<NV, 256>>>();
    k_post1<<<dim3(NV / 128, HV, 4), 128>>>(W_out);
    k_scal<<<NV / 256, 256>>>();
    k_lin<<<dim3(NV / 64, 5), 256>>>();
    k_final<<<NV / 8, 256>>>(out);
}

// round 9
// speedup vs baseline: 1.1182x; 1.1182x over previous
#include <cuda_runtime.h>
#include <cuda_bf16.h>
#include <math.h>

#define NV    6144
#define HV    4
#define EPSV  1e-7f
#define MINV  1e-15f
#define NSEG  32
#define SEGR  192
#define CAP   24
#define AST   68
#define WLN   320

// ---------------- scratch ----------------
__device__ int   g_cnt[NV * NSEG];
__device__ int   g_nbr[(size_t)NV * NSEG * CAP];
__device__ float g_att[(size_t)HV * NV * AST];  // [0..63] raw att ov; [64..67]=t_att,sh_att,t_dat,sh_dat
__device__ float g_dat[(size_t)HV * NV * AST];  // [0..63] raw dat ov
__device__ float g_osqF[16 * NV];               // k_feat partial osq [osel*8+m][node]
__device__ float g_u  [(size_t)HV * NV * 64];   // node-major mobius logmap vectors
__device__ float g_pcT[(size_t)256 * NV];       // feature-major RAW Wo outputs
__device__ float g_osqP[16 * NV];               // k_post1 partial osq [osel*4+h][node]
__device__ float g_as [HV * NV];                // fused per-(head,node) scale
__device__ float g_pre[(size_t)NV * WLN];
__device__ float g_WlP[256 * WLN];              // W_lin^T padded (zeros beyond 260)

// ---------------- helpers ----------------
__device__ __forceinline__ float wred(float v) {
#pragma unroll
    for (int o = 16; o; o >>= 1) v += __shfl_xor_sync(0xffffffffu, v, o);
    return v;
}
__device__ __forceinline__ float acoshr(float z) {          // precise (node-level uses)
    float t = fmaxf(z * z - 1.0f, 0.0f);
    return logf(z + sqrtf(t));
}
__device__ __forceinline__ float acoshf_fast(float z) {     // fast (per-edge hot path)
    float t = fmaxf(z * z - 1.0f, 0.0f);
    return __logf(z + sqrtf(t));
}

// ---------------- K1: neighbor lists + W_lin transpose ----------------
__global__ __launch_bounds__(256) void k_build(const float* __restrict__ adj,
                                               const float* __restrict__ Wl) {
    if (blockIdx.y == NSEG) {
        for (int e = blockIdx.x * 256 + threadIdx.x; e < 256 * 260; e += 24 * 256) {
            int kk = e / 260, n = e % 260;
            g_WlP[(size_t)kk * WLN + n] = Wl[n * 257 + kk + 1];
        }
        return;
    }
    int c   = blockIdx.x * 256 + threadIdx.x;
    int seg = blockIdx.y;
    int cnt = 0;
    size_t base = ((size_t)c * NSEG + seg) * CAP;
    int j0 = seg * SEGR;
    for (int r = 0; r < SEGR; r += 8) {
        float v[8];
#pragma unroll
        for (int u = 0; u < 8; u++) v[u] = adj[(size_t)(j0 + r + u) * NV + c];
#pragma unroll
        for (int u = 0; u < 8; u++) {
            if (v[u] > 0.01f) {
                if (cnt < CAP) g_nbr[base + cnt] = j0 + r + u;
                cnt++;
            }
        }
    }
    g_cnt[c * NSEG + seg] = (cnt < CAP) ? cnt : CAP;
}

// ---------------- K2: hyp_linear att/data -> RAW half-rows + partial osq ------
#define SMEM_FEAT ((8320 + 2048) * 4)

__global__ __launch_bounds__(128) void k_feat(const float* __restrict__ x,
                                              const float* __restrict__ Wa,
                                              const float* __restrict__ Wd) {
    extern __shared__ float sm[];
    float*  su  = sm;                 // 128*65
    float*  sW  = sm + 8320;          // 32*64
    float4* sW4 = (float4*)sW;
    int t = threadIdx.x;
    int m = blockIdx.y, h = m & 3, osel = blockIdx.z;
    const float* W = (m < 4) ? (Wa + h * 4225) : (Wd + h * 4225);
    int nb = blockIdx.x * 128;

    for (int e = t; e < 128 * 65; e += 128) su[e] = x[(size_t)nb * 65 + e];
    for (int e = t; e < 32 * 64; e += 128) {
        int oo = e >> 6, c = e & 63;
        sW[e] = W[(osel * 32 + oo + 1) * 65 + 1 + c];
    }
    __syncthreads();

    float u[64];
    float x0 = su[t * 65];
    float q0 = 0.f, q1 = 0.f, q2 = 0.f, q3 = 0.f;
#pragma unroll
    for (int c = 0; c < 64; c += 4) {
        float a = su[t * 65 + 1 + c], b = su[t * 65 + 2 + c];
        float cc = su[t * 65 + 3 + c], d = su[t * 65 + 4 + c];
        u[c] = a; u[c + 1] = b; u[c + 2] = cc; u[c + 3] = d;
        q0 += a * a; q1 += b * b; q2 += cc * cc; q3 += d * d;
    }
    float nsq = (q0 + q1) + (q2 + q3);
    float scale = acoshr(fmaxf(x0, 1.0f + EPSV)) / fmaxf(sqrtf(nsq), MINV);
#pragma unroll
    for (int c = 0; c < 64; c++) u[c] *= scale;

    float* dst = (m < 4) ? g_att : g_dat;
    float* R = dst + ((size_t)(h * NV) + nb + t) * AST + osel * 32;
    float osq = 0.f;
#pragma unroll 2
    for (int o4 = 0; o4 < 8; o4++) {
        float4 ov4;
        float* po = (float*)&ov4;
#pragma unroll
        for (int jj = 0; jj < 4; jj++) {
            int oo = o4 * 4 + jj;
            float a0 = 0.f, a1 = 0.f, a2 = 0.f, a3 = 0.f;
#pragma unroll
            for (int c4 = 0; c4 < 16; c4++) {
                float4 wv = sW4[oo * 16 + c4];
                a0 += wv.x * u[4 * c4];
                a1 += wv.y * u[4 * c4 + 1];
                a2 += wv.z * u[4 * c4 + 2];
                a3 += wv.w * u[4 * c4 + 3];
            }
            float ov = (a0 + a1) + (a2 + a3);
            po[jj] = ov;
            osq += ov * ov;
        }
        *(float4*)&R[o4 * 4] = ov4;
    }
    g_osqF[(osel * 8 + m) * NV + nb + t] = osq;
}

// ---------------- K2b: combine osq -> t/sh extras in g_att rows --------------
__global__ __launch_bounds__(256) void k_ts(void) {
    int node = blockIdx.x * 256 + threadIdx.x;
    int m = blockIdx.y, h = m & 3;
    float osq = g_osqF[m * NV + node] + g_osqF[(8 + m) * NV + node];
    float n2 = fmaxf(sqrtf(osq), MINV);
    float shv = sinhf(n2) / n2;
    float tv = sqrtf(1.0f + shv * shv * osq);
    float* R = g_att + ((size_t)(h * NV) + node) * AST + ((m < 4) ? 64 : 66);
    R[0] = tv;
    R[1] = shv;
}

// ---------------- K3: sparse attention + mobius -> g_u (node-major) ----------
__global__ __launch_bounds__(128) void k_attn(void) {
    int i = blockIdx.x;
    int w = threadIdx.x >> 5, l = threadIdx.x & 31;
    int h = w;
    int s = l & 7, g = l >> 3;
    __shared__ int slist[800];
    __shared__ int stot;

    if (threadIdx.x < 32) {
        int c = g_cnt[i * NSEG + l];
        int sc = c;
#pragma unroll
        for (int o = 1; o < 32; o <<= 1) {
            int v = __shfl_up_sync(0xffffffffu, sc, o);
            if (l >= o) sc += v;
        }
        int off = sc - c;
        const int* lst = g_nbr + ((size_t)i * NSEG + l) * CAP;
        for (int k = 0; k < c; k++) slist[off + k] = lst[k];
        if (l == 31) stot = sc;
    }
    __syncthreads();
    int nk = stot;
    int nk4 = (nk + 3) & ~3;
    if (threadIdx.x < nk4 - nk) slist[nk + threadIdx.x] = slist[0];
    __syncthreads();

    const float* Ai = g_att + ((size_t)(h * NV) + i) * AST;
    float4 ei = *(const float4*)(Ai + 64);   // t_att, sh_att, t_dat, sh_dat
    float ai0 = ei.x, shA_i = ei.y;
    float4 a0 = *(const float4*)(Ai + 8 * s);
    float4 a1 = *(const float4*)(Ai + 8 * s + 4);
    a0.x *= shA_i; a0.y *= shA_i; a0.z *= shA_i; a0.w *= shA_i;
    a1.x *= shA_i; a1.y *= shA_i; a1.z *= shA_i; a1.w *= shA_i;

    float T1 = 0.f, T2 = 0.f, Up = 0.f, Qp = 0.f;
    for (int kc = 0; kc < nk4; kc += 4) {
        int j = slist[kc + g];
        const float* Aj = g_att + ((size_t)(h * NV) + j) * AST;
        float4 b0 = *(const float4*)(Aj + 8 * s);
        float4 b1 = *(const float4*)(Aj + 8 * s + 4);
        float4 ej = *(const float4*)(Aj + 64);
        float part = a0.x * b0.x + a0.y * b0.y + a0.z * b0.z + a0.w * b0.w
                   + a1.x * b1.x + a1.y * b1.y + a1.z * b1.z + a1.w * b1.w;
#pragma unroll
        for (int o = 4; o; o >>= 1) part += __shfl_xor_sync(0xffffffffu, part, o);
        float th = fmaxf(ai0 * ej.x - ej.y * part, 1.0f + EPSV);
        float ar = acoshf_fast(th);
        float S = fminf(ar * ar, 50.0f);
        if (kc + g >= nk) S = 0.0f;
        Up += S * ej.z;          // S * (lam-1) = S * t_dat
        Qp += S * S;
        float Sgs = S * ej.w;    // S * sh_dat
#pragma unroll
        for (int gg = 0; gg < 4; gg++) {
            float Sg = __shfl_sync(0xffffffffu, Sgs, gg * 8 + s);
            int jg = slist[kc + gg];
            const float* Dj = g_dat + ((size_t)(h * NV) + jg) * AST;
            T1 += Sg * Dj[l];
            T2 += Sg * Dj[l + 32];
        }
    }
    float U = wred(Up) * 0.125f;
    float Q = wred(Qp) * 0.125f;

    float nrm = fmaxf(sqrtf(Q), 1e-12f);
    float den = fmaxf(U / nrm, MINV);
    float v1 = (-T1 / nrm) / den, v2 = (-T2 / nrm) / den;
    float nvsq = wred(v1 * v1 + v2 * v2);
    float nv = fmaxf(sqrtf(nvsq), MINV);
    float ncl = fminf(nv, 1.0f - EPSV);
    float f = tanhf(0.5f * atanhf(ncl)) / nv;
    float m1 = f * v1, m2 = f * v2;
    float s2 = f * f * nvsq;
    float dd = fmaxf(1.0f - s2, MINV);
    float hb0 = (1.0f + s2) / dd;
    float nyy = fmaxf(2.0f * sqrtf(s2) / dd, MINV);
    float sc2 = acoshr(fmaxf(hb0, 1.0f + EPSV)) * (2.0f / dd) / nyy;
    float* Uo = g_u + ((size_t)(h * NV) + i) * 64;
    Uo[l]      = sc2 * m1;
    Uo[l + 32] = sc2 * m2;
}

// ---------------- K4: Wo matvec, node-per-thread, 4-way o-split --------------
__global__ __launch_bounds__(128) void k_post1(const float* __restrict__ Wo) {
    __shared__ float sW[16 * 64];
    float4* sW4 = (float4*)sW;
    int t = threadIdx.x;
    int h = blockIdx.y, osel = blockIdx.z;
    int node = blockIdx.x * 128 + t;

    for (int e = t; e < 16 * 64; e += 128) {
        int o2 = e >> 6, c = e & 63;
        sW[e] = Wo[h * 4225 + (osel * 16 + o2 + 1) * 65 + 1 + c];
    }
    __syncthreads();

    float u[64];
    const float4* U4 = (const float4*)(g_u + ((size_t)(h * NV) + node) * 64);
#pragma unroll
    for (int c4 = 0; c4 < 16; c4++) {
        float4 v = U4[c4];
        u[4 * c4] = v.x; u[4 * c4 + 1] = v.y; u[4 * c4 + 2] = v.z; u[4 * c4 + 3] = v.w;
    }

    float osq = 0.f;
#pragma unroll 2
    for (int o2 = 0; o2 < 16; o2++) {
        float a0 = 0.f, a1 = 0.f, a2 = 0.f, a3 = 0.f;
#pragma unroll
        for (int c4 = 0; c4 < 16; c4++) {
            float4 wv = sW4[o2 * 16 + c4];
            a0 += wv.x * u[4 * c4];
            a1 += wv.y * u[4 * c4 + 1];
            a2 += wv.z * u[4 * c4 + 2];
            a3 += wv.w * u[4 * c4 + 3];
        }
        float ov = (a0 + a1) + (a2 + a3);
        g_pcT[(size_t)(h * 64 + osel * 16 + o2) * NV + node] = ov;
        osq += ov * ov;
    }
    g_osqP[(osel * 4 + h) * NV + node] = osq;
}

// ---------------- K5: fused per-(head,node) scale ----------------
__global__ __launch_bounds__(256) void k_scal(void) {
    int node = blockIdx.x * 256 + threadIdx.x;
    float cn[HV];
    float ssum = 0.f;
#pragma unroll
    for (int h = 0; h < HV; h++) {
        float osq = g_osqP[h * NV + node] + g_osqP[(4 + h) * NV + node]
                  + g_osqP[(8 + h) * NV + node] + g_osqP[(12 + h) * NV + node];
        float n2 = fmaxf(sqrtf(osq), MINV);
        float sh = sinhf(n2) / n2;
        float tv = sqrtf(1.0f + sh * sh * osq);
        cn[h] = sh / (tv + 1.0f);
        ssum += cn[h] * cn[h] * osq;
    }
    float dd = fmaxf(1.0f - ssum, MINV);
    float hb0 = (1.0f + ssum) / dd;
    float nyy = fmaxf(2.0f * sqrtf(ssum) / dd, MINV);
    float srow = acoshr(fmaxf(hb0, 1.0f + EPSV)) * (2.0f / dd) / nyy;
#pragma unroll
    for (int h = 0; h < HV; h++) g_as[h * NV + node] = cn[h] * srow;
}

// ---------------- K6: SGEMM 64x64x16, scale fused on A load ------------------
__global__ __launch_bounds__(256) void k_lin(void) {
    __shared__ float As[16][68];
    __shared__ float Bs[16][64];
    __shared__ float sAS[4][64];
    int t = threadIdx.x;
    int i0 = blockIdx.x * 64, n0 = blockIdx.y * 64;
    int tx = t & 15, ty = t >> 4;
    int ak = t >> 4, an4 = t & 15;
    float acc[4][4];
#pragma unroll
    for (int i = 0; i < 4; i++)
#pragma unroll
        for (int j = 0; j < 4; j++) acc[i][j] = 0.f;

    {
        int h = t >> 6, n = t & 63;
        sAS[h][n] = g_as[h * NV + i0 + n];
    }
    __syncthreads();

    for (int k0 = 0; k0 < 256; k0 += 16) {
        int hh = k0 >> 6;
        __syncthreads();
        float4 av = *(const float4*)&g_pcT[(size_t)(k0 + ak) * NV + i0 + an4 * 4];
        float4 sv = *(const float4*)&sAS[hh][an4 * 4];
        As[ak][an4 * 4 + 0] = av.x * sv.x;
        As[ak][an4 * 4 + 1] = av.y * sv.y;
        As[ak][an4 * 4 + 2] = av.z * sv.z;
        As[ak][an4 * 4 + 3] = av.w * sv.w;
        *(float4*)&Bs[ak][an4 * 4] =
            *(const float4*)&g_WlP[(size_t)(k0 + ak) * WLN + n0 + an4 * 4];
        __syncthreads();
#pragma unroll
        for (int k = 0; k < 16; k++) {
            float4 a = *(const float4*)&As[k][ty * 4];
            float4 b = *(const float4*)&Bs[k][tx * 4];
            acc[0][0] += a.x * b.x; acc[0][1] += a.x * b.y; acc[0][2] += a.x * b.z; acc[0][3] += a.x * b.w;
            acc[1][0] += a.y * b.x; acc[1][1] += a.y * b.y; acc[1][2] += a.y * b.z; acc[1][3] += a.y * b.w;
            acc[2][0] += a.z * b.x; acc[2][1] += a.z * b.y; acc[2][2] += a.z * b.z; acc[2][3] += a.z * b.w;
            acc[3][0] += a.w * b.x; acc[3][1] += a.w * b.y; acc[3][2] += a.w * b.z; acc[3][3] += a.w * b.w;
        }
    }
#pragma unroll
    for (int i = 0; i < 4; i++) {
        float4 v = make_float4(acc[i][0], acc[i][1], acc[i][2], acc[i][3]);
        *(float4*)&g_pre[(size_t)(i0 + ty * 4 + i) * WLN + n0 + tx * 4] = v;
    }
}

// ---------------- K7: final expmap0 + hyp_proj ----------------
__global__ __launch_bounds__(256) void k_final(float* __restrict__ out) {
    int w = threadIdx.x >> 5, l = threadIdx.x & 31;
    int row = blockIdx.x * 8 + w;
    float v[8], q = 0.f;
#pragma unroll
    for (int k = 0; k < 8; k++) {
        v[k] = g_pre[(size_t)row * WLN + k * 32 + l];
        if (!(k == 0 && l == 0)) q += v[k] * v[k];
    }
    float t4 = 0.f;
    if (l < 4) { t4 = g_pre[(size_t)row * WLN + 256 + l]; q += t4 * t4; }
    q = wred(q);
    float n2 = fmaxf(sqrtf(q), MINV);
    float sh = sinhf(n2) / n2;
    float tv = sqrtf(1.0f + sh * sh * q);
#pragma unroll
    for (int k = 0; k < 8; k++) {
        float o = (k == 0 && l == 0) ? tv : sh * v[k];
        out[(size_t)row * 260 + k * 32 + l] = o;
    }
    if (l < 4) out[(size_t)row * 260 + 256 + l] = sh * t4;
}

// ---------------- launch ----------------
extern "C" void kernel_launch(void* const* d_in, const int* in_sizes, int n_in,
                              void* d_out, int out_size) {
    const float* x     = (const float*)d_in[0];
    const float* adj   = (const float*)d_in[1];
    const float* W_att = (const float*)d_in[2];
    const float* W_dat = (const float*)d_in[3];
    const float* W_out = (const float*)d_in[4];
    const float* W_lin = (const float*)d_in[5];
    float* out = (float*)d_out;

    cudaFuncSetAttribute(k_feat, cudaFuncAttributeMaxDynamicSharedMemorySize, SMEM_FEAT);

    k_build<<<dim3(NV / 256, NSEG + 1), 256>>>(adj, W_lin);
    k_feat<<<dim3(NV / 128, 8, 2), 128, SMEM_FEAT>>>(x, W_att, W_dat);
    k_ts<<<dim3(NV / 256, 8), 256>>>();
    k_attn<<<NV, 128>>>();
    k_post1<<<dim3(NV / 128, HV, 4), 128>>>(W_out);
    k_scal<<<NV / 256, 256>>>();
    k_lin<<<dim3(NV / 64, 5), 256>>>();
    k_final<<<NV / 8, 256>>>(out);
}

// round 10
// speedup vs baseline: 1.1218x; 1.0032x over previous
#include <cuda_runtime.h>
#include <cuda_bf16.h>
#include <math.h>

#define NV    6144
#define HV    4
#define EPSV  1e-7f
#define MINV  1e-15f
#define NSEG  32
#define SEGR  192
#define CAP   24
#define AST   68
#define WLN   320

// ---------------- scratch ----------------
__device__ int   g_cnt[NV * NSEG];
__device__ int   g_nbr[(size_t)NV * NSEG * CAP];
__device__ float g_att[(size_t)HV * NV * AST];  // [0..63] raw att ov; [64..67]=t_att,sh_att,t_dat,sh_dat
__device__ float g_dat[(size_t)HV * NV * AST];  // [0..63] raw dat ov
__device__ float g_osqF[16 * NV];               // k_feat partial osq [osel*8+m][node]
__device__ float g_u  [(size_t)HV * NV * 64];   // node-major mobius logmap vectors
__device__ float g_pcT[(size_t)256 * NV];       // feature-major RAW Wo outputs
__device__ float g_osqP[16 * NV];               // k_post1 partial osq [osel*4+h][node]
__device__ float g_as [HV * NV];                // fused per-(head,node) scale
__device__ float g_pre[(size_t)NV * WLN];
__device__ float g_WlP[256 * WLN];              // W_lin^T padded (zeros beyond 260)

// ---------------- helpers ----------------
__device__ __forceinline__ float wred(float v) {
#pragma unroll
    for (int o = 16; o; o >>= 1) v += __shfl_xor_sync(0xffffffffu, v, o);
    return v;
}
__device__ __forceinline__ float acoshr(float z) {          // precise (node-level uses)
    float t = fmaxf(z * z - 1.0f, 0.0f);
    return logf(z + sqrtf(t));
}
__device__ __forceinline__ float acoshf_fast(float z) {     // fast (per-edge hot path)
    float t = fmaxf(z * z - 1.0f, 0.0f);
    return __logf(z + sqrtf(t));
}

// ---------------- K1: neighbor lists + W_lin transpose ----------------
__global__ __launch_bounds__(256) void k_build(const float* __restrict__ adj,
                                               const float* __restrict__ Wl) {
    if (blockIdx.y == NSEG) {
        for (int e = blockIdx.x * 256 + threadIdx.x; e < 256 * 260; e += 24 * 256) {
            int kk = e / 260, n = e % 260;
            g_WlP[(size_t)kk * WLN + n] = Wl[n * 257 + kk + 1];
        }
        return;
    }
    int c   = blockIdx.x * 256 + threadIdx.x;
    int seg = blockIdx.y;
    int cnt = 0;
    size_t base = ((size_t)c * NSEG + seg) * CAP;
    int j0 = seg * SEGR;
    for (int r = 0; r < SEGR; r += 8) {
        float v[8];
#pragma unroll
        for (int u = 0; u < 8; u++) v[u] = adj[(size_t)(j0 + r + u) * NV + c];
#pragma unroll
        for (int u = 0; u < 8; u++) {
            if (v[u] > 0.01f) {
                if (cnt < CAP) g_nbr[base + cnt] = j0 + r + u;
                cnt++;
            }
        }
    }
    g_cnt[c * NSEG + seg] = (cnt < CAP) ? cnt : CAP;
}

// ---------------- K2: hyp_linear att/data -> RAW half-rows + partial osq ------
#define SMEM_FEAT ((8320 + 2048) * 4)

__global__ __launch_bounds__(128) void k_feat(const float* __restrict__ x,
                                              const float* __restrict__ Wa,
                                              const float* __restrict__ Wd) {
    extern __shared__ float sm[];
    float*  su  = sm;                 // 128*65
    float*  sW  = sm + 8320;          // 32*64
    float4* sW4 = (float4*)sW;
    int t = threadIdx.x;
    int m = blockIdx.y, h = m & 3, osel = blockIdx.z;
    const float* W = (m < 4) ? (Wa + h * 4225) : (Wd + h * 4225);
    int nb = blockIdx.x * 128;

    for (int e = t; e < 128 * 65; e += 128) su[e] = x[(size_t)nb * 65 + e];
    for (int e = t; e < 32 * 64; e += 128) {
        int oo = e >> 6, c = e & 63;
        sW[e] = W[(osel * 32 + oo + 1) * 65 + 1 + c];
    }
    __syncthreads();

    float u[64];
    float x0 = su[t * 65];
    float q0 = 0.f, q1 = 0.f, q2 = 0.f, q3 = 0.f;
#pragma unroll
    for (int c = 0; c < 64; c += 4) {
        float a = su[t * 65 + 1 + c], b = su[t * 65 + 2 + c];
        float cc = su[t * 65 + 3 + c], d = su[t * 65 + 4 + c];
        u[c] = a; u[c + 1] = b; u[c + 2] = cc; u[c + 3] = d;
        q0 += a * a; q1 += b * b; q2 += cc * cc; q3 += d * d;
    }
    float nsq = (q0 + q1) + (q2 + q3);
    float scale = acoshr(fmaxf(x0, 1.0f + EPSV)) / fmaxf(sqrtf(nsq), MINV);
#pragma unroll
    for (int c = 0; c < 64; c++) u[c] *= scale;

    float* dst = (m < 4) ? g_att : g_dat;
    float* R = dst + ((size_t)(h * NV) + nb + t) * AST + osel * 32;
    float osq = 0.f;
#pragma unroll 2
    for (int o4 = 0; o4 < 8; o4++) {
        float4 ov4;
        float* po = (float*)&ov4;
#pragma unroll
        for (int jj = 0; jj < 4; jj++) {
            int oo = o4 * 4 + jj;
            float a0 = 0.f, a1 = 0.f, a2 = 0.f, a3 = 0.f;
#pragma unroll
            for (int c4 = 0; c4 < 16; c4++) {
                float4 wv = sW4[oo * 16 + c4];
                a0 += wv.x * u[4 * c4];
                a1 += wv.y * u[4 * c4 + 1];
                a2 += wv.z * u[4 * c4 + 2];
                a3 += wv.w * u[4 * c4 + 3];
            }
            float ov = (a0 + a1) + (a2 + a3);
            po[jj] = ov;
            osq += ov * ov;
        }
        *(float4*)&R[o4 * 4] = ov4;
    }
    g_osqF[(osel * 8 + m) * NV + nb + t] = osq;
}

// ---------------- K2b: combine osq -> t/sh extras in g_att rows --------------
__global__ __launch_bounds__(256) void k_ts(void) {
    int node = blockIdx.x * 256 + threadIdx.x;
    int m = blockIdx.y, h = m & 3;
    float osq = g_osqF[m * NV + node] + g_osqF[(8 + m) * NV + node];
    float n2 = fmaxf(sqrtf(osq), MINV);
    float shv = sinhf(n2) / n2;
    float tv = sqrtf(1.0f + shv * shv * osq);
    float* R = g_att + ((size_t)(h * NV) + node) * AST + ((m < 4) ? 64 : 66);
    R[0] = tv;
    R[1] = shv;
}

// ---------------- K3: sparse attention + mobius -> g_u (node-major) ----------
// 4 warps (one head each); groups of 4 lanes, 8 neighbors per iteration.
__global__ __launch_bounds__(128) void k_attn(void) {
    int i = blockIdx.x;
    int w = threadIdx.x >> 5, l = threadIdx.x & 31;
    int h = w;
    int s = l & 3, g = l >> 2;      // feature quarter, neighbor slot (0..7)
    __shared__ int slist[808];
    __shared__ int stot;

    if (threadIdx.x < 32) {
        int c = g_cnt[i * NSEG + l];
        int sc = c;
#pragma unroll
        for (int o = 1; o < 32; o <<= 1) {
            int v = __shfl_up_sync(0xffffffffu, sc, o);
            if (l >= o) sc += v;
        }
        int off = sc - c;
        const int* lst = g_nbr + ((size_t)i * NSEG + l) * CAP;
        for (int k = 0; k < c; k++) slist[off + k] = lst[k];
        if (l == 31) stot = sc;
    }
    __syncthreads();
    int nk = stot;
    int nk8 = (nk + 7) & ~7;
    if (threadIdx.x < nk8 - nk) slist[nk + threadIdx.x] = slist[0];
    __syncthreads();

    const float* Ai = g_att + ((size_t)(h * NV) + i) * AST;
    float4 ei = *(const float4*)(Ai + 64);   // t_att, sh_att, t_dat, sh_dat
    float ai0 = ei.x, shA_i = ei.y;
    // lane's 16-feature quarter of row i, pre-scaled by sh_att_i
    float4 a0 = *(const float4*)(Ai + 16 * s);
    float4 a1 = *(const float4*)(Ai + 16 * s + 4);
    float4 a2 = *(const float4*)(Ai + 16 * s + 8);
    float4 a3 = *(const float4*)(Ai + 16 * s + 12);
    a0.x *= shA_i; a0.y *= shA_i; a0.z *= shA_i; a0.w *= shA_i;
    a1.x *= shA_i; a1.y *= shA_i; a1.z *= shA_i; a1.w *= shA_i;
    a2.x *= shA_i; a2.y *= shA_i; a2.z *= shA_i; a2.w *= shA_i;
    a3.x *= shA_i; a3.y *= shA_i; a3.z *= shA_i; a3.w *= shA_i;

    float T1 = 0.f, T2 = 0.f, Up = 0.f, Qp = 0.f;
    for (int kc = 0; kc < nk8; kc += 8) {
        int j = slist[kc + g];
        const float* Aj = g_att + ((size_t)(h * NV) + j) * AST;

        // hoisted independent loads: D rows for all 8 neighbors (addr from slist only)
        float d1[8], d2[8];
#pragma unroll
        for (int gg = 0; gg < 8; gg++) {
            int jg = slist[kc + gg];
            const float* Dj = g_dat + ((size_t)(h * NV) + jg) * AST;
            d1[gg] = Dj[l];
            d2[gg] = Dj[l + 32];
        }

        float4 b0 = *(const float4*)(Aj + 16 * s);
        float4 b1 = *(const float4*)(Aj + 16 * s + 4);
        float4 b2 = *(const float4*)(Aj + 16 * s + 8);
        float4 b3 = *(const float4*)(Aj + 16 * s + 12);
        float4 ej = *(const float4*)(Aj + 64);
        float part = a0.x * b0.x + a0.y * b0.y + a0.z * b0.z + a0.w * b0.w
                   + a1.x * b1.x + a1.y * b1.y + a1.z * b1.z + a1.w * b1.w
                   + a2.x * b2.x + a2.y * b2.y + a2.z * b2.z + a2.w * b2.w
                   + a3.x * b3.x + a3.y * b3.y + a3.z * b3.z + a3.w * b3.w;
        part += __shfl_xor_sync(0xffffffffu, part, 1);
        part += __shfl_xor_sync(0xffffffffu, part, 2);
        float th = fmaxf(ai0 * ej.x - ej.y * part, 1.0f + EPSV);
        float ar = acoshf_fast(th);
        float S = fminf(ar * ar, 50.0f);
        if (kc + g >= nk) S = 0.0f;
        Up += S * ej.z;          // S * (lam-1) = S * t_dat
        Qp += S * S;
        float Sgs = S * ej.w;    // S * sh_dat
#pragma unroll
        for (int gg = 0; gg < 8; gg++) {
            float Sg = __shfl_sync(0xffffffffu, Sgs, gg * 4);
            T1 += Sg * d1[gg];
            T2 += Sg * d2[gg];
        }
    }
    float U = wred(Up) * 0.25f;   // each neighbor counted by its 4 group lanes
    float Q = wred(Qp) * 0.25f;

    float nrm = fmaxf(sqrtf(Q), 1e-12f);
    float den = fmaxf(U / nrm, MINV);
    float v1 = (-T1 / nrm) / den, v2 = (-T2 / nrm) / den;
    float nvsq = wred(v1 * v1 + v2 * v2);
    float nv = fmaxf(sqrtf(nvsq), MINV);
    float ncl = fminf(nv, 1.0f - EPSV);
    // tanh(0.5*atanh(n)) = n / (1 + sqrt(1 - n^2))  (exact identity)
    float f = ncl / ((1.0f + sqrtf(fmaxf(1.0f - ncl * ncl, 0.0f))) * nv);
    float m1 = f * v1, m2 = f * v2;
    float s2 = f * f * nvsq;
    float dd = fmaxf(1.0f - s2, MINV);
    float hb0 = (1.0f + s2) / dd;
    float nyy = fmaxf(2.0f * sqrtf(s2) / dd, MINV);
    float sc2 = acoshr(fmaxf(hb0, 1.0f + EPSV)) * (2.0f / dd) / nyy;
    float* Uo = g_u + ((size_t)(h * NV) + i) * 64;
    Uo[l]      = sc2 * m1;
    Uo[l + 32] = sc2 * m2;
}

// ---------------- K4: Wo matvec, node-per-thread, 4-way o-split --------------
__global__ __launch_bounds__(128) void k_post1(const float* __restrict__ Wo) {
    __shared__ float sW[16 * 64];
    float4* sW4 = (float4*)sW;
    int t = threadIdx.x;
    int h = blockIdx.y, osel = blockIdx.z;
    int node = blockIdx.x * 128 + t;

    for (int e = t; e < 16 * 64; e += 128) {
        int o2 = e >> 6, c = e & 63;
        sW[e] = Wo[h * 4225 + (osel * 16 + o2 + 1) * 65 + 1 + c];
    }
    __syncthreads();

    float u[64];
    const float4* U4 = (const float4*)(g_u + ((size_t)(h * NV) + node) * 64);
#pragma unroll
    for (int c4 = 0; c4 < 16; c4++) {
        float4 v = U4[c4];
        u[4 * c4] = v.x; u[4 * c4 + 1] = v.y; u[4 * c4 + 2] = v.z; u[4 * c4 + 3] = v.w;
    }

    float osq = 0.f;
#pragma unroll 2
    for (int o2 = 0; o2 < 16; o2++) {
        float a0 = 0.f, a1 = 0.f, a2 = 0.f, a3 = 0.f;
#pragma unroll
        for (int c4 = 0; c4 < 16; c4++) {
            float4 wv = sW4[o2 * 16 + c4];
            a0 += wv.x * u[4 * c4];
            a1 += wv.y * u[4 * c4 + 1];
            a2 += wv.z * u[4 * c4 + 2];
            a3 += wv.w * u[4 * c4 + 3];
        }
        float ov = (a0 + a1) + (a2 + a3);
        g_pcT[(size_t)(h * 64 + osel * 16 + o2) * NV + node] = ov;
        osq += ov * ov;
    }
    g_osqP[(osel * 4 + h) * NV + node] = osq;
}

// ---------------- K5: fused per-(head,node) scale ----------------
__global__ __launch_bounds__(256) void k_scal(void) {
    int node = blockIdx.x * 256 + threadIdx.x;
    float cn[HV];
    float ssum = 0.f;
#pragma unroll
    for (int h = 0; h < HV; h++) {
        float osq = g_osqP[h * NV + node] + g_osqP[(4 + h) * NV + node]
                  + g_osqP[(8 + h) * NV + node] + g_osqP[(12 + h) * NV + node];
        float n2 = fmaxf(sqrtf(osq), MINV);
        float sh = sinhf(n2) / n2;
        float tv = sqrtf(1.0f + sh * sh * osq);
        cn[h] = sh / (tv + 1.0f);
        ssum += cn[h] * cn[h] * osq;
    }
    float dd = fmaxf(1.0f - ssum, MINV);
    float hb0 = (1.0f + ssum) / dd;
    float nyy = fmaxf(2.0f * sqrtf(ssum) / dd, MINV);
    float srow = acoshr(fmaxf(hb0, 1.0f + EPSV)) * (2.0f / dd) / nyy;
#pragma unroll
    for (int h = 0; h < HV; h++) g_as[h * NV + node] = cn[h] * srow;
}

// ---------------- K6: SGEMM 64x64x16, scale fused on A load ------------------
__global__ __launch_bounds__(256) void k_lin(void) {
    __shared__ float As[16][68];
    __shared__ float Bs[16][64];
    __shared__ float sAS[4][64];
    int t = threadIdx.x;
    int i0 = blockIdx.x * 64, n0 = blockIdx.y * 64;
    int tx = t & 15, ty = t >> 4;
    int ak = t >> 4, an4 = t & 15;
    float acc[4][4];
#pragma unroll
    for (int i = 0; i < 4; i++)
#pragma unroll
        for (int j = 0; j < 4; j++) acc[i][j] = 0.f;

    {
        int h = t >> 6, n = t & 63;
        sAS[h][n] = g_as[h * NV + i0 + n];
    }
    __syncthreads();

    for (int k0 = 0; k0 < 256; k0 += 16) {
        int hh = k0 >> 6;
        __syncthreads();
        float4 av = *(const float4*)&g_pcT[(size_t)(k0 + ak) * NV + i0 + an4 * 4];
        float4 sv = *(const float4*)&sAS[hh][an4 * 4];
        As[ak][an4 * 4 + 0] = av.x * sv.x;
        As[ak][an4 * 4 + 1] = av.y * sv.y;
        As[ak][an4 * 4 + 2] = av.z * sv.z;
        As[ak][an4 * 4 + 3] = av.w * sv.w;
        *(float4*)&Bs[ak][an4 * 4] =
            *(const float4*)&g_WlP[(size_t)(k0 + ak) * WLN + n0 + an4 * 4];
        __syncthreads();
#pragma unroll
        for (int k = 0; k < 16; k++) {
            float4 a = *(const float4*)&As[k][ty * 4];
            float4 b = *(const float4*)&Bs[k][tx * 4];
            acc[0][0] += a.x * b.x; acc[0][1] += a.x * b.y; acc[0][2] += a.x * b.z; acc[0][3] += a.x * b.w;
            acc[1][0] += a.y * b.x; acc[1][1] += a.y * b.y; acc[1][2] += a.y * b.z; acc[1][3] += a.y * b.w;
            acc[2][0] += a.z * b.x; acc[2][1] += a.z * b.y; acc[2][2] += a.z * b.z; acc[2][3] += a.z * b.w;
            acc[3][0] += a.w * b.x; acc[3][1] += a.w * b.y; acc[3][2] += a.w * b.z; acc[3][3] += a.w * b.w;
        }
    }
#pragma unroll
    for (int i = 0; i < 4; i++) {
        float4 v = make_float4(acc[i][0], acc[i][1], acc[i][2], acc[i][3]);
        *(float4*)&g_pre[(size_t)(i0 + ty * 4 + i) * WLN + n0 + tx * 4] = v;
    }
}

// ---------------- K7: final expmap0 + hyp_proj ----------------
__global__ __launch_bounds__(256) void k_final(float* __restrict__ out) {
    int w = threadIdx.x >> 5, l = threadIdx.x & 31;
    int row = blockIdx.x * 8 + w;
    float v[8], q = 0.f;
#pragma unroll
    for (int k = 0; k < 8; k++) {
        v[k] = g_pre[(size_t)row * WLN + k * 32 + l];
        if (!(k == 0 && l == 0)) q += v[k] * v[k];
    }
    float t4 = 0.f;
    if (l < 4) { t4 = g_pre[(size_t)row * WLN + 256 + l]; q += t4 * t4; }
    q = wred(q);
    float n2 = fmaxf(sqrtf(q), MINV);
    float sh = sinhf(n2) / n2;
    float tv = sqrtf(1.0f + sh * sh * q);
#pragma unroll
    for (int k = 0; k < 8; k++) {
        float o = (k == 0 && l == 0) ? tv : sh * v[k];
        out[(size_t)row * 260 + k * 32 + l] = o;
    }
    if (l < 4) out[(size_t)row * 260 + 256 + l] = sh * t4;
}

// ---------------- launch ----------------
extern "C" void kernel_launch(void* const* d_in, const int* in_sizes, int n_in,
                              void* d_out, int out_size) {
    const float* x     = (const float*)d_in[0];
    const float* adj   = (const float*)d_in[1];
    const float* W_att = (const float*)d_in[2];
    const float* W_dat = (const float*)d_in[3];
    const float* W_out = (const float*)d_in[4];
    const float* W_lin = (const float*)d_in[5];
    float* out = (float*)d_out;

    cudaFuncSetAttribute(k_feat, cudaFuncAttributeMaxDynamicSharedMemorySize, SMEM_FEAT);

    k_build<<<dim3(NV / 256, NSEG + 1), 256>>>(adj, W_lin);
    k_feat<<<dim3(NV / 128, 8, 2), 128, SMEM_FEAT>>>(x, W_att, W_dat);
    k_ts<<<dim3(NV / 256, 8), 256>>>();
    k_attn<<<NV, 128>>>();
    k_post1<<<dim3(NV / 128, HV, 4), 128>>>(W_out);
    k_scal<<<NV / 256, 256>>>();
    k_lin<<<dim3(NV / 64, 5), 256>>>();
    k_final<<<NV / 8, 256>>>(out);
}